// round 7
// baseline (speedup 1.0000x reference)
#include <cuda_runtime.h>
#include <cstdint>

#define B 16
#define I 256
#define T 8192
#define NSTEP 8189   // T-3 sampled steps
#define TOUT  8190   // T-2 output length

#define NCHAIN 4
#define BPC (B / NCHAIN)      // batches per chain = 4
#define ROWS_PC (BPC * I)     // rows per chain = 1024

// Scratch (static __device__ arrays; no allocation anywhere)
__device__ unsigned char g_nsp[B * T];       // [b][t]: bits0-1 = normal, bit2 = special-1
__device__ unsigned char g_delta[B * T];     // [b][jo]: gather delta in {0,1,2}

// ---------------- Threefry-2x32 (JAX-exact) ----------------
__device__ __forceinline__ void tf2x32(uint32_t k1, uint32_t k2,
                                       uint32_t c0, uint32_t c1,
                                       uint32_t& o0, uint32_t& o1) {
    uint32_t ks2 = k1 ^ k2 ^ 0x1BD11BDAu;
    uint32_t x0 = c0 + k1;
    uint32_t x1 = c1 + k2;
#define TFR(r) { x0 += x1; x1 = __funnelshift_l(x1, x1, (r)); x1 ^= x0; }
    TFR(13) TFR(15) TFR(26) TFR(6)
    x0 += k2;  x1 += ks2 + 1u;
    TFR(17) TFR(29) TFR(16) TFR(24)
    x0 += ks2; x1 += k1 + 2u;
    TFR(13) TFR(15) TFR(26) TFR(6)
    x0 += k1;  x1 += k2 + 3u;
    TFR(17) TFR(29) TFR(16) TFR(24)
    x0 += k2;  x1 += ks2 + 4u;
    TFR(13) TFR(15) TFR(26) TFR(6)
    x0 += ks2; x1 += k1 + 5u;
#undef TFR
    o0 = x0; o1 = x1;
}

// gumbel from 32 random bits, replicating jax._src.random._uniform + gumbel
__device__ __forceinline__ float gumbel_bits(uint32_t bits) {
    const float TINY = 1.17549435e-38f;   // finfo(float32).tiny
    float f = __uint_as_float((bits >> 9) | 0x3F800000u) - 1.0f;  // [0,1)
    float u = fmaxf(TINY, f + TINY);
    return -logf(-logf(u));
}

// ---------------- Kernel 1: draws for one chain (4 batches) ----------------
// 768 threads = 64 t x 4 b x 3 k. Each thread does ONE draw threefry+gumbel;
// keys deduped via smem; k==0 threads combine the three gumbels.
__global__ __launch_bounds__(768) void kgen(const int* __restrict__ seedp, int g) {
    __shared__ uint2 skey[64];
    __shared__ float sg[3 * 256];

    int tid = threadIdx.x;
    int k   = tid >> 8;                 // 0..2
    int idx = tid & 255;                // (bb, tt)
    int tt  = idx & 63;
    int bb  = idx >> 6;                 // 0..3
    int b   = g * BPC + bb;
    int t   = blockIdx.x * 64 + tt;

    uint32_t seed_lo = (uint32_t)(*seedp);  // threefry_seed: k1 = seed>>32 = 0

    if (tid < 64) {
        uint32_t kx, ky;
        tf2x32(0u, seed_lo, 0u, (uint32_t)(blockIdx.x * 64 + tid), kx, ky);
        skey[tid] = make_uint2(kx, ky);
    }
    __syncthreads();

    uint2 key = skey[tt];
    uint32_t o0, o1;
    tf2x32(key.x, key.y, 0u, (uint32_t)(b * 3 + k), o0, o1);
    sg[k * 256 + idx] = gumbel_bits(o0 ^ o1);
    __syncthreads();

    if (k == 0 && t < NSTEP) {
        float g0 = sg[idx];
        float g1 = sg[256 + idx];
        float g2 = sg[512 + idx];

        const double pd = 0.1, sd = 1.0 - 2.0 * 0.1;
        float lp  = logf(0.1f);
        float ls  = logf(0.8f);
        float l1s = logf((float)(sd / (pd + sd)));  // special row k=1
        float l2s = logf((float)(pd / (pd + sd)));  // special row k=2  (k=0 -inf)

        // normal row argmax (first max wins)
        float v0 = g0 + lp, v1 = g1 + ls, v2 = g2 + lp;
        int n = 0; float best = v0;
        if (v1 > best) { best = v1; n = 1; }
        if (v2 > best) { n = 2; }

        // special row argmax over {1,2}
        int sp = (g2 + l2s > g1 + l1s) ? 2 : 1;

        g_nsp[b * T + t] = (unsigned char)(n | ((sp - 1) << 2));
    }
}

// ---------------- Kernel 2: parallel FSM scan, one block per batch ----------
__global__ __launch_bounds__(512) void kscan(int g) {
    int b = g * BPC + blockIdx.x;
    int j = threadIdx.x;               // 0..511, chunk of 16 steps
    __shared__ uint32_t maps[512];

    uint4 wv = *reinterpret_cast<const uint4*>(g_nsp + b * T + j * 16);
    uint32_t w[4] = {wv.x, wv.y, wv.z, wv.w};

    int nvalid = NSTEP - j * 16;
    if (nvalid > 16) nvalid = 16;

    uint32_t f0, f1, f2, f3;
    {
        uint32_t byt = w[0] & 0xFFu;
        uint32_t n = byt & 3u, sp = 1u + ((byt >> 2) & 1u);
        f0 = n; f1 = 3u + n; f2 = 6u + n; f3 = 6u + sp;
    }
    for (int s = 1; s < nvalid; s++) {
        uint32_t byt = (w[s >> 2] >> ((s & 3) * 8)) & 0xFFu;
        uint32_t n = byt & 3u, sp = 1u + ((byt >> 2) & 1u);
        f0 = (f0 % 3u) * 3u + ((f0 == 5u) ? sp : n);
        f1 = (f1 % 3u) * 3u + ((f1 == 5u) ? sp : n);
        f2 = (f2 % 3u) * 3u + ((f2 == 5u) ? sp : n);
        f3 = (f3 % 3u) * 3u + ((f3 == 5u) ? sp : n);
    }
    maps[j] = f0 | (f1 << 8) | (f2 << 16) | (f3 << 24);
    __syncthreads();

    for (int off = 1; off < 512; off <<= 1) {
        uint32_t prev = (j >= off) ? maps[j - off] : 0u;
        __syncthreads();
        if (j >= off) {
            uint32_t cur = maps[j];
            uint32_t nm = 0u;
#pragma unroll
            for (int c = 0; c < 4; c++) {
                uint32_t pv = (prev >> (8 * c)) & 0xFFu;
                uint32_t cl = (pv == 5u) ? 3u : (pv % 3u);
                nm |= (((cur >> (8 * cl)) & 0xFFu) << (8 * c));
            }
            maps[j] = nm;
        }
        __syncthreads();
    }

    uint32_t v = (j == 0) ? 4u : ((maps[j - 1] >> 8) & 0xFFu);

    unsigned char* dp = g_delta + b * T;
    if (j == 0) dp[0] = 1;
#pragma unroll
    for (int s = 0; s < 16; s++) {
        int t = j * 16 + s;
        if (t < NSTEP) {
            uint32_t byt = (w[s >> 2] >> ((s & 3) * 8)) & 0xFFu;
            uint32_t n = byt & 3u, sp = 1u + ((byt >> 2) & 1u);
            uint32_t ch = (v == 5u) ? sp : n;
            dp[t + 1] = (unsigned char)ch;
            v = (v % 3u) * 3u + ch;
        }
    }
}

// ---------------- Kernel 3: barrier-free warp gather, 8 outputs/thread ----
__global__ __launch_bounds__(256) void kgather(const float* __restrict__ x,
                                               float* __restrict__ y, int g) {
    int gw   = blockIdx.x * 8 + (threadIdx.x >> 5);  // warp id within chain
    int lane = threadIdx.x & 31;
    int row  = g * ROWS_PC + (gw >> 5);              // b*I + i (32 warps/row)
    int wseg = gw & 31;
    int wb   = wseg << 8;                            // warp base within row
    int b    = row >> 8;
    bool last = (wseg == 31);                        // row tail warp

    const float* xr = x + (size_t)row * T + wb;
    float4 a = __ldcs(reinterpret_cast<const float4*>(xr) + lane * 2);
    float4 c = __ldcs(reinterpret_cast<const float4*>(xr) + lane * 2 + 1);
    uint2 dd = *reinterpret_cast<const uint2*>(g_delta + (size_t)b * T + wb + lane * 8);

    float ex0 = 0.f, ex1 = 0.f;
    if (!last && lane == 0) {
        float2 e = __ldg(reinterpret_cast<const float2*>(xr + 256));
        ex0 = e.x; ex1 = e.y;
    }
    ex0 = __shfl_sync(0xFFFFFFFFu, ex0, 0);
    ex1 = __shfl_sync(0xFFFFFFFFu, ex1, 0);

    float nx = __shfl_down_sync(0xFFFFFFFFu, a.x, 1);
    float ny = __shfl_down_sync(0xFFFFFFFFu, a.y, 1);
    if (lane == 31) { nx = ex0; ny = ex1; }

    float rr[10] = {a.x, a.y, a.z, a.w, c.x, c.y, c.z, c.w, nx, ny};
    float o[8];
#pragma unroll
    for (int q = 0; q < 8; q++) {
        uint32_t d = ((q < 4 ? dd.x >> (8 * q) : dd.y >> (8 * (q - 4))) & 3u);
        o[q] = (d == 0) ? rr[q] : ((d == 1) ? rr[q + 1] : rr[q + 2]);
    }

    float* yr = y + (size_t)row * TOUT + wb + lane * 8;
    bool tail = last && (lane == 31);
    if (!tail) {
        if ((row & 1) == 0) {
            __stcs(reinterpret_cast<float4*>(yr),     make_float4(o[0], o[1], o[2], o[3]));
            __stcs(reinterpret_cast<float4*>(yr) + 1, make_float4(o[4], o[5], o[6], o[7]));
        } else {
            __stcs(reinterpret_cast<float2*>(yr),     make_float2(o[0], o[1]));
            __stcs(reinterpret_cast<float2*>(yr) + 1, make_float2(o[2], o[3]));
            __stcs(reinterpret_cast<float2*>(yr) + 2, make_float2(o[4], o[5]));
            __stcs(reinterpret_cast<float2*>(yr) + 3, make_float2(o[6], o[7]));
        }
    } else {
        __stcs(reinterpret_cast<float2*>(yr),     make_float2(o[0], o[1]));
        __stcs(reinterpret_cast<float2*>(yr) + 1, make_float2(o[2], o[3]));
        __stcs(reinterpret_cast<float2*>(yr) + 2, make_float2(o[4], o[5]));
    }
}

// ---------------- Streams/events: created once at load, before harness ----
// (no device memory allocation; handles only)
struct ChainStreams {
    cudaStream_t s[NCHAIN - 1];
    cudaEvent_t  fork;
    cudaEvent_t  join[NCHAIN - 1];
    ChainStreams() {
        for (int i = 0; i < NCHAIN - 1; i++)
            cudaStreamCreateWithFlags(&s[i], cudaStreamNonBlocking);
        cudaEventCreateWithFlags(&fork, cudaEventDisableTiming);
        for (int i = 0; i < NCHAIN - 1; i++)
            cudaEventCreateWithFlags(&join[i], cudaEventDisableTiming);
    }
};
static ChainStreams g_cs;

extern "C" void kernel_launch(void* const* d_in, const int* in_sizes, int n_in,
                              void* d_out, int out_size) {
    const float* x   = (const float*)d_in[0];
    const int* seedp = (const int*)d_in[1];
    float* y = (float*)d_out;

    // fork side chains off the launch (capture) stream
    cudaEventRecord(g_cs.fork, 0);
    for (int i = 0; i < NCHAIN - 1; i++)
        cudaStreamWaitEvent(g_cs.s[i], g_cs.fork, 0);

    for (int g = 0; g < NCHAIN; g++) {
        cudaStream_t st = (g == 0) ? 0 : g_cs.s[g - 1];
        kgen<<<(NSTEP + 63) / 64, 768, 0, st>>>(seedp, g);
        kscan<<<BPC, 512, 0, st>>>(g);
        kgather<<<(ROWS_PC * 32) / 8, 256, 0, st>>>(x, y, g);
    }

    // join side chains back into the launch stream
    for (int i = 0; i < NCHAIN - 1; i++) {
        cudaEventRecord(g_cs.join[i], g_cs.s[i]);
        cudaStreamWaitEvent(0, g_cs.join[i], 0);
    }
}

// round 8
// speedup vs baseline: 1.0912x; 1.0912x over previous
#include <cuda_runtime.h>
#include <cstdint>

#define B 16
#define I 256
#define T 8192
#define NSTEP 8189   // T-3 sampled steps
#define TOUT  8190   // T-2 output length

#define BPC 8                 // batches per chain (2 chains)
#define ROWS_PC (BPC * I)     // rows per chain = 2048

// Scratch (static __device__ arrays; no allocation anywhere)
__device__ unsigned char g_nsp[B * T];       // [b][t]: bits0-1 = normal, bit2 = special-1
__device__ unsigned char g_delta[B * T];     // [b][jo]: gather delta in {0,1,2}

// ---------------- Threefry-2x32 (JAX-exact) ----------------
__device__ __forceinline__ void tf2x32(uint32_t k1, uint32_t k2,
                                       uint32_t c0, uint32_t c1,
                                       uint32_t& o0, uint32_t& o1) {
    uint32_t ks2 = k1 ^ k2 ^ 0x1BD11BDAu;
    uint32_t x0 = c0 + k1;
    uint32_t x1 = c1 + k2;
#define TFR(r) { x0 += x1; x1 = __funnelshift_l(x1, x1, (r)); x1 ^= x0; }
    TFR(13) TFR(15) TFR(26) TFR(6)
    x0 += k2;  x1 += ks2 + 1u;
    TFR(17) TFR(29) TFR(16) TFR(24)
    x0 += ks2; x1 += k1 + 2u;
    TFR(13) TFR(15) TFR(26) TFR(6)
    x0 += k1;  x1 += k2 + 3u;
    TFR(17) TFR(29) TFR(16) TFR(24)
    x0 += k2;  x1 += ks2 + 4u;
    TFR(13) TFR(15) TFR(26) TFR(6)
    x0 += ks2; x1 += k1 + 5u;
#undef TFR
    o0 = x0; o1 = x1;
}

// gumbel from 32 random bits, replicating jax._src.random._uniform + gumbel
__device__ __forceinline__ float gumbel_bits(uint32_t bits) {
    const float TINY = 1.17549435e-38f;   // finfo(float32).tiny
    float f = __uint_as_float((bits >> 9) | 0x3F800000u) - 1.0f;  // [0,1)
    float u = fmaxf(TINY, f + TINY);
    return -logf(-logf(u));
}

// ---------------- Kernel 1: draws for one chain (8 batches) ----------------
// 768 threads = 32 t x 8 b x 3 k. One draw threefry+gumbel per thread;
// per-step keys deduped via smem; k==0 threads combine the three gumbels.
__global__ __launch_bounds__(768) void kgen(const int* __restrict__ seedp, int b0) {
    __shared__ uint2 skey[32];
    __shared__ float sg[3 * 256];

    int tid = threadIdx.x;
    int k   = tid >> 8;                 // 0..2
    int idx = tid & 255;                // (bb, tt)
    int tt  = idx & 31;
    int bb  = idx >> 5;                 // 0..7
    int b   = b0 + bb;
    int t   = blockIdx.x * 32 + tt;

    uint32_t seed_lo = (uint32_t)(*seedp);  // threefry_seed: k1 = seed>>32 = 0

    if (tid < 32) {
        uint32_t kx, ky;
        tf2x32(0u, seed_lo, 0u, (uint32_t)(blockIdx.x * 32 + tid), kx, ky);
        skey[tid] = make_uint2(kx, ky);
    }
    __syncthreads();

    uint2 key = skey[tt];
    uint32_t o0, o1;
    tf2x32(key.x, key.y, 0u, (uint32_t)(b * 3 + k), o0, o1);
    sg[k * 256 + idx] = gumbel_bits(o0 ^ o1);
    __syncthreads();

    if (k == 0 && t < NSTEP) {
        float g0 = sg[idx];
        float g1 = sg[256 + idx];
        float g2 = sg[512 + idx];

        const double pd = 0.1, sd = 1.0 - 2.0 * 0.1;
        float lp  = logf(0.1f);
        float ls  = logf(0.8f);
        float l1s = logf((float)(sd / (pd + sd)));  // special row k=1
        float l2s = logf((float)(pd / (pd + sd)));  // special row k=2  (k=0 -inf)

        // normal row argmax (first max wins)
        float v0 = g0 + lp, v1 = g1 + ls, v2 = g2 + lp;
        int n = 0; float best = v0;
        if (v1 > best) { best = v1; n = 1; }
        if (v2 > best) { n = 2; }

        // special row argmax over {1,2}
        int sp = (g2 + l2s > g1 + l1s) ? 2 : 1;

        g_nsp[b * T + t] = (unsigned char)(n | ((sp - 1) << 2));
    }
}

// ---------------- FSM map composition: prev then cur ----------------
// map = 4 bytes, byte c = state reached from class c. class(v) = LUT:
// v:0..8 -> 0,1,2,0,1,3,0,1,2  packed 2b each = 0x24D24.
__device__ __forceinline__ uint32_t compose(uint32_t prev, uint32_t cur) {
    uint32_t sel = 0;
#pragma unroll
    for (int c = 0; c < 4; c++) {
        uint32_t pv = (prev >> (8 * c)) & 0xFFu;
        uint32_t cl = (0x24D24u >> (pv * 2)) & 3u;
        sel |= cl << (4 * c);
    }
    return __byte_perm(cur, 0u, sel);
}

// ---------------- Kernel 2: shfl-based parallel FSM scan, 1 block/batch ----
__global__ __launch_bounds__(512) void kscan(int b0) {
    int b = b0 + blockIdx.x;
    int j = threadIdx.x;               // 0..511, chunk of 16 steps
    int lane = j & 31, warp = j >> 5;  // 16 warps
    __shared__ uint32_t wtot[16];
    __shared__ uint32_t incl_s[512];

    uint4 wv = *reinterpret_cast<const uint4*>(g_nsp + b * T + j * 16);
    uint32_t w[4] = {wv.x, wv.y, wv.z, wv.w};

    int nvalid = NSTEP - j * 16;
    if (nvalid > 16) nvalid = 16;      // every thread has >= 1 valid step

    // chunk function: class (0..3) -> resulting state
    uint32_t f0, f1, f2, f3;
    {
        uint32_t byt = w[0] & 0xFFu;
        uint32_t n = byt & 3u, sp = 1u + ((byt >> 2) & 1u);
        f0 = n; f1 = 3u + n; f2 = 6u + n; f3 = 6u + sp;
    }
    for (int s = 1; s < nvalid; s++) {
        uint32_t byt = (w[s >> 2] >> ((s & 3) * 8)) & 0xFFu;
        uint32_t n = byt & 3u, sp = 1u + ((byt >> 2) & 1u);
        f0 = (f0 % 3u) * 3u + ((f0 == 5u) ? sp : n);
        f1 = (f1 % 3u) * 3u + ((f1 == 5u) ? sp : n);
        f2 = (f2 % 3u) * 3u + ((f2 == 5u) ? sp : n);
        f3 = (f3 % 3u) * 3u + ((f3 == 5u) ? sp : n);
    }
    uint32_t incl = f0 | (f1 << 8) | (f2 << 16) | (f3 << 24);

    // warp-level inclusive scan of composition
#pragma unroll
    for (int off = 1; off < 32; off <<= 1) {
        uint32_t p = __shfl_up_sync(0xFFFFFFFFu, incl, off);
        if (lane >= off) incl = compose(p, incl);
    }
    if (lane == 31) wtot[warp] = incl;
    __syncthreads();

    // warp 0 scans the 16 warp totals
    if (warp == 0) {
        uint32_t v = (lane < 16) ? wtot[lane] : 0u;
#pragma unroll
        for (int off = 1; off < 16; off <<= 1) {
            uint32_t p = __shfl_up_sync(0xFFFFFFFFu, v, off);
            if (lane >= off) v = compose(p, v);
        }
        if (lane < 16) wtot[lane] = v;
    }
    __syncthreads();

    if (warp > 0) incl = compose(wtot[warp - 1], incl);
    incl_s[j] = incl;
    __syncthreads();

    // entry state: apply prefix (chunks 0..j-1) to init state 4 (class 1)
    uint32_t v = (j == 0) ? 4u : ((incl_s[j - 1] >> 8) & 0xFFu);

    unsigned char* dp = g_delta + b * T;
    if (j == 0) dp[0] = 1;             // jo=0 fixed index 1
#pragma unroll
    for (int s = 0; s < 16; s++) {
        int t = j * 16 + s;
        if (t < NSTEP) {
            uint32_t byt = (w[s >> 2] >> ((s & 3) * 8)) & 0xFFu;
            uint32_t n = byt & 3u, sp = 1u + ((byt >> 2) & 1u);
            uint32_t ch = (v == 5u) ? sp : n;
            dp[t + 1] = (unsigned char)ch;
            v = (v % 3u) * 3u + ch;
        }
    }
}

// ---------------- Kernel 3: barrier-free warp gather, 8 outputs/thread ----
__global__ __launch_bounds__(256) void kgather(const float* __restrict__ x,
                                               float* __restrict__ y, int b0) {
    int gw   = blockIdx.x * 8 + (threadIdx.x >> 5);  // warp id within chain
    int lane = threadIdx.x & 31;
    int row  = b0 * I + (gw >> 5);                   // b*I + i (32 warps/row)
    int wseg = gw & 31;
    int wb   = wseg << 8;                            // warp base within row
    int b    = row >> 8;
    bool last = (wseg == 31);                        // row tail warp

    const float* xr = x + (size_t)row * T + wb;
    float4 a = __ldcs(reinterpret_cast<const float4*>(xr) + lane * 2);
    float4 c = __ldcs(reinterpret_cast<const float4*>(xr) + lane * 2 + 1);
    uint2 dd = *reinterpret_cast<const uint2*>(g_delta + (size_t)b * T + wb + lane * 8);

    float ex0 = 0.f, ex1 = 0.f;
    if (!last && lane == 0) {
        float2 e = __ldg(reinterpret_cast<const float2*>(xr + 256));
        ex0 = e.x; ex1 = e.y;
    }
    ex0 = __shfl_sync(0xFFFFFFFFu, ex0, 0);
    ex1 = __shfl_sync(0xFFFFFFFFu, ex1, 0);

    float nx = __shfl_down_sync(0xFFFFFFFFu, a.x, 1);
    float ny = __shfl_down_sync(0xFFFFFFFFu, a.y, 1);
    if (lane == 31) { nx = ex0; ny = ex1; }

    float rr[10] = {a.x, a.y, a.z, a.w, c.x, c.y, c.z, c.w, nx, ny};
    float o[8];
#pragma unroll
    for (int q = 0; q < 8; q++) {
        uint32_t d = ((q < 4 ? dd.x >> (8 * q) : dd.y >> (8 * (q - 4))) & 3u);
        o[q] = (d == 0) ? rr[q] : ((d == 1) ? rr[q + 1] : rr[q + 2]);
    }

    float* yr = y + (size_t)row * TOUT + wb + lane * 8;
    bool tail = last && (lane == 31);
    if (!tail) {
        if ((row & 1) == 0) {
            __stcs(reinterpret_cast<float4*>(yr),     make_float4(o[0], o[1], o[2], o[3]));
            __stcs(reinterpret_cast<float4*>(yr) + 1, make_float4(o[4], o[5], o[6], o[7]));
        } else {
            __stcs(reinterpret_cast<float2*>(yr),     make_float2(o[0], o[1]));
            __stcs(reinterpret_cast<float2*>(yr) + 1, make_float2(o[2], o[3]));
            __stcs(reinterpret_cast<float2*>(yr) + 2, make_float2(o[4], o[5]));
            __stcs(reinterpret_cast<float2*>(yr) + 3, make_float2(o[6], o[7]));
        }
    } else {
        __stcs(reinterpret_cast<float2*>(yr),     make_float2(o[0], o[1]));
        __stcs(reinterpret_cast<float2*>(yr) + 1, make_float2(o[2], o[3]));
        __stcs(reinterpret_cast<float2*>(yr) + 2, make_float2(o[4], o[5]));
    }
}

// ---------------- One extra stream + 2 events (handles only, no dev mem) ---
struct ChainStreams {
    cudaStream_t s1;
    cudaEvent_t  fork, join;
    ChainStreams() {
        cudaStreamCreateWithFlags(&s1, cudaStreamNonBlocking);
        cudaEventCreateWithFlags(&fork, cudaEventDisableTiming);
        cudaEventCreateWithFlags(&join, cudaEventDisableTiming);
    }
};
static ChainStreams g_cs;

extern "C" void kernel_launch(void* const* d_in, const int* in_sizes, int n_in,
                              void* d_out, int out_size) {
    const float* x   = (const float*)d_in[0];
    const int* seedp = (const int*)d_in[1];
    float* y = (float*)d_out;

    cudaEventRecord(g_cs.fork, 0);
    cudaStreamWaitEvent(g_cs.s1, g_cs.fork, 0);

    // prologues first (adjacent in submission order), then gathers
    kgen<<<(NSTEP + 31) / 32, 768, 0, 0>>>(seedp, 0);
    kgen<<<(NSTEP + 31) / 32, 768, 0, g_cs.s1>>>(seedp, BPC);
    kscan<<<BPC, 512, 0, 0>>>(0);
    kscan<<<BPC, 512, 0, g_cs.s1>>>(BPC);
    kgather<<<(ROWS_PC * 32) / 8, 256, 0, 0>>>(x, y, 0);
    kgather<<<(ROWS_PC * 32) / 8, 256, 0, g_cs.s1>>>(x, y, BPC);

    cudaEventRecord(g_cs.join, g_cs.s1);
    cudaStreamWaitEvent(0, g_cs.join, 0);
}

// round 9
// speedup vs baseline: 1.1340x; 1.0393x over previous
#include <cuda_runtime.h>
#include <cstdint>

#define B 16
#define I 256
#define T 8192
#define NSTEP 8189   // T-3 sampled steps
#define TOUT  8190   // T-2 output length

#define BPC 8                 // batches per chain (2 chains)
#define ROWS_PC (BPC * I)     // rows per chain = 2048

// Scratch (static __device__ arrays; no allocation anywhere)
__device__ unsigned char g_nsp[B * T];       // [b][t]: bits0-1 = normal, bit2 = special-1
__device__ unsigned char g_delta[B * T];     // [b][jo]: gather delta in {0,1,2}

// ---------------- Threefry-2x32 (JAX-exact) ----------------
__device__ __forceinline__ void tf2x32(uint32_t k1, uint32_t k2,
                                       uint32_t c0, uint32_t c1,
                                       uint32_t& o0, uint32_t& o1) {
    uint32_t ks2 = k1 ^ k2 ^ 0x1BD11BDAu;
    uint32_t x0 = c0 + k1;
    uint32_t x1 = c1 + k2;
#define TFR(r) { x0 += x1; x1 = __funnelshift_l(x1, x1, (r)); x1 ^= x0; }
    TFR(13) TFR(15) TFR(26) TFR(6)
    x0 += k2;  x1 += ks2 + 1u;
    TFR(17) TFR(29) TFR(16) TFR(24)
    x0 += ks2; x1 += k1 + 2u;
    TFR(13) TFR(15) TFR(26) TFR(6)
    x0 += k1;  x1 += k2 + 3u;
    TFR(17) TFR(29) TFR(16) TFR(24)
    x0 += k2;  x1 += ks2 + 4u;
    TFR(13) TFR(15) TFR(26) TFR(6)
    x0 += ks2; x1 += k1 + 5u;
#undef TFR
    o0 = x0; o1 = x1;
}

// gumbel from 32 random bits, replicating jax._src.random._uniform + gumbel
__device__ __forceinline__ float gumbel_bits(uint32_t bits) {
    const float TINY = 1.17549435e-38f;   // finfo(float32).tiny
    float f = __uint_as_float((bits >> 9) | 0x3F800000u) - 1.0f;  // [0,1)
    float u = fmaxf(TINY, f + TINY);
    return -logf(-logf(u));
}

// ---------------- Kernel 1: draws for one chain (8 batches) ----------------
// 768 threads = 32 t x 8 b x 3 k. One draw threefry+gumbel per thread;
// per-step keys deduped via smem; k==0 threads combine the three gumbels.
__global__ __launch_bounds__(768) void kgen(const int* __restrict__ seedp, int b0) {
    __shared__ uint2 skey[32];
    __shared__ float sg[3 * 256];

    int tid = threadIdx.x;
    int k   = tid >> 8;                 // 0..2
    int idx = tid & 255;                // (bb, tt)
    int tt  = idx & 31;
    int bb  = idx >> 5;                 // 0..7
    int b   = b0 + bb;
    int t   = blockIdx.x * 32 + tt;

    uint32_t seed_lo = (uint32_t)(*seedp);  // threefry_seed: k1 = seed>>32 = 0

    if (tid < 32) {
        uint32_t kx, ky;
        tf2x32(0u, seed_lo, 0u, (uint32_t)(blockIdx.x * 32 + tid), kx, ky);
        skey[tid] = make_uint2(kx, ky);
    }
    __syncthreads();

    uint2 key = skey[tt];
    uint32_t o0, o1;
    tf2x32(key.x, key.y, 0u, (uint32_t)(b * 3 + k), o0, o1);
    sg[k * 256 + idx] = gumbel_bits(o0 ^ o1);
    __syncthreads();

    if (k == 0 && t < NSTEP) {
        float g0 = sg[idx];
        float g1 = sg[256 + idx];
        float g2 = sg[512 + idx];

        const double pd = 0.1, sd = 1.0 - 2.0 * 0.1;
        float lp  = logf(0.1f);
        float ls  = logf(0.8f);
        float l1s = logf((float)(sd / (pd + sd)));  // special row k=1
        float l2s = logf((float)(pd / (pd + sd)));  // special row k=2  (k=0 -inf)

        // normal row argmax (first max wins)
        float v0 = g0 + lp, v1 = g1 + ls, v2 = g2 + lp;
        int n = 0; float best = v0;
        if (v1 > best) { best = v1; n = 1; }
        if (v2 > best) { n = 2; }

        // special row argmax over {1,2}
        int sp = (g2 + l2s > g1 + l1s) ? 2 : 1;

        g_nsp[b * T + t] = (unsigned char)(n | ((sp - 1) << 2));
    }
}

// ---------------- FSM map machinery ----------------
// map = 4 bytes, byte c = state reached from class c.
// class(v), v in 0..8 -> 0,1,2,0,1,3,0,1,2  packed 2b each = 0x24D24.
__device__ __forceinline__ uint32_t compose(uint32_t prev, uint32_t cur) {
    uint32_t sel = 0;
#pragma unroll
    for (int c = 0; c < 4; c++) {
        uint32_t pv = (prev >> (8 * c)) & 0xFFu;
        uint32_t cl = (0x24D24u >> (pv * 2)) & 3u;
        sel |= cl << (4 * c);
    }
    return __byte_perm(cur, 0u, sel);
}

// single-step map from an nsp byte: classes (0,1,2,3) -> (n, 3+n, 6+n, 6+sp)
__device__ __forceinline__ uint32_t stepmap(uint32_t byt) {
    uint32_t n = byt & 3u;
    return n * 0x00010101u + 0x00060300u + ((7u + ((byt >> 2) & 1u)) << 24);
}

// ---------------- Kernel 2: shfl-based parallel FSM scan, 1 block/batch ----
// 1024 threads x 8 steps: short serial chunk, compose-based chunk build.
__global__ __launch_bounds__(1024) void kscan(int b0) {
    int b = b0 + blockIdx.x;
    int j = threadIdx.x;               // 0..1023, chunk of 8 steps
    int lane = j & 31, warp = j >> 5;  // 32 warps
    __shared__ uint32_t wtot[32];
    __shared__ uint32_t incl_s[1024];

    uint2 wv = __ldg(reinterpret_cast<const uint2*>(g_nsp + b * T + j * 8));
    uint32_t w[2] = {wv.x, wv.y};

    int nvalid = NSTEP - j * 8;
    if (nvalid > 8) nvalid = 8;        // every thread has >= 1 valid step

    uint32_t incl = stepmap(w[0] & 0xFFu);
#pragma unroll
    for (int s = 1; s < 8; s++) {
        if (s < nvalid) {
            uint32_t byt = (w[s >> 2] >> ((s & 3) * 8)) & 0xFFu;
            incl = compose(incl, stepmap(byt));
        }
    }

    // warp-level inclusive scan of composition
#pragma unroll
    for (int off = 1; off < 32; off <<= 1) {
        uint32_t p = __shfl_up_sync(0xFFFFFFFFu, incl, off);
        if (lane >= off) incl = compose(p, incl);
    }
    if (lane == 31) wtot[warp] = incl;
    __syncthreads();

    // warp 0 scans the 32 warp totals
    if (warp == 0) {
        uint32_t v = wtot[lane];
#pragma unroll
        for (int off = 1; off < 32; off <<= 1) {
            uint32_t p = __shfl_up_sync(0xFFFFFFFFu, v, off);
            if (lane >= off) v = compose(p, v);
        }
        wtot[lane] = v;
    }
    __syncthreads();

    if (warp > 0) incl = compose(wtot[warp - 1], incl);
    incl_s[j] = incl;
    __syncthreads();

    // entry state: apply prefix (chunks 0..j-1) to init state 4 (class 1)
    uint32_t v = (j == 0) ? 4u : ((incl_s[j - 1] >> 8) & 0xFFu);

    unsigned char* dp = g_delta + b * T;
    if (j == 0) dp[0] = 1;             // jo=0 fixed index 1
#pragma unroll
    for (int s = 0; s < 8; s++) {
        int t = j * 8 + s;
        if (t < NSTEP) {
            uint32_t byt = (w[s >> 2] >> ((s & 3) * 8)) & 0xFFu;
            uint32_t n = byt & 3u, sp = 1u + ((byt >> 2) & 1u);
            uint32_t ch = (v == 5u) ? sp : n;
            dp[t + 1] = (unsigned char)ch;
            v = (v % 3u) * 3u + ch;
        }
    }
}

// ---------------- Kernel 3: barrier-free warp gather, 8 outputs/thread ----
__global__ __launch_bounds__(256) void kgather(const float* __restrict__ x,
                                               float* __restrict__ y, int b0) {
    int gw   = blockIdx.x * 8 + (threadIdx.x >> 5);  // warp id within chain
    int lane = threadIdx.x & 31;
    int row  = b0 * I + (gw >> 5);                   // b*I + i (32 warps/row)
    int wseg = gw & 31;
    int wb   = wseg << 8;                            // warp base within row
    int b    = row >> 8;
    bool last = (wseg == 31);                        // row tail warp

    const float* xr = x + (size_t)row * T + wb;
    float4 a = __ldcs(reinterpret_cast<const float4*>(xr) + lane * 2);
    float4 c = __ldcs(reinterpret_cast<const float4*>(xr) + lane * 2 + 1);
    uint2 dd = *reinterpret_cast<const uint2*>(g_delta + (size_t)b * T + wb + lane * 8);

    float ex0 = 0.f, ex1 = 0.f;
    if (!last && lane == 0) {
        float2 e = __ldg(reinterpret_cast<const float2*>(xr + 256));
        ex0 = e.x; ex1 = e.y;
    }
    ex0 = __shfl_sync(0xFFFFFFFFu, ex0, 0);
    ex1 = __shfl_sync(0xFFFFFFFFu, ex1, 0);

    float nx = __shfl_down_sync(0xFFFFFFFFu, a.x, 1);
    float ny = __shfl_down_sync(0xFFFFFFFFu, a.y, 1);
    if (lane == 31) { nx = ex0; ny = ex1; }

    float rr[10] = {a.x, a.y, a.z, a.w, c.x, c.y, c.z, c.w, nx, ny};
    float o[8];
#pragma unroll
    for (int q = 0; q < 8; q++) {
        uint32_t d = ((q < 4 ? dd.x >> (8 * q) : dd.y >> (8 * (q - 4))) & 3u);
        o[q] = (d == 0) ? rr[q] : ((d == 1) ? rr[q + 1] : rr[q + 2]);
    }

    float* yr = y + (size_t)row * TOUT + wb + lane * 8;
    bool tail = last && (lane == 31);
    if (!tail) {
        if ((row & 1) == 0) {
            __stcs(reinterpret_cast<float4*>(yr),     make_float4(o[0], o[1], o[2], o[3]));
            __stcs(reinterpret_cast<float4*>(yr) + 1, make_float4(o[4], o[5], o[6], o[7]));
        } else {
            __stcs(reinterpret_cast<float2*>(yr),     make_float2(o[0], o[1]));
            __stcs(reinterpret_cast<float2*>(yr) + 1, make_float2(o[2], o[3]));
            __stcs(reinterpret_cast<float2*>(yr) + 2, make_float2(o[4], o[5]));
            __stcs(reinterpret_cast<float2*>(yr) + 3, make_float2(o[6], o[7]));
        }
    } else {
        __stcs(reinterpret_cast<float2*>(yr),     make_float2(o[0], o[1]));
        __stcs(reinterpret_cast<float2*>(yr) + 1, make_float2(o[2], o[3]));
        __stcs(reinterpret_cast<float2*>(yr) + 2, make_float2(o[4], o[5]));
    }
}

// ---------------- One extra stream + 2 events (handles only, no dev mem) ---
struct ChainStreams {
    cudaStream_t s1;
    cudaEvent_t  fork, join;
    ChainStreams() {
        cudaStreamCreateWithFlags(&s1, cudaStreamNonBlocking);
        cudaEventCreateWithFlags(&fork, cudaEventDisableTiming);
        cudaEventCreateWithFlags(&join, cudaEventDisableTiming);
    }
};
static ChainStreams g_cs;

extern "C" void kernel_launch(void* const* d_in, const int* in_sizes, int n_in,
                              void* d_out, int out_size) {
    const float* x   = (const float*)d_in[0];
    const int* seedp = (const int*)d_in[1];
    float* y = (float*)d_out;

    cudaEventRecord(g_cs.fork, 0);
    cudaStreamWaitEvent(g_cs.s1, g_cs.fork, 0);

    // prologues first (adjacent in submission order), then gathers
    kgen<<<(NSTEP + 31) / 32, 768, 0, 0>>>(seedp, 0);
    kgen<<<(NSTEP + 31) / 32, 768, 0, g_cs.s1>>>(seedp, BPC);
    kscan<<<BPC, 1024, 0, 0>>>(0);
    kscan<<<BPC, 1024, 0, g_cs.s1>>>(BPC);
    kgather<<<(ROWS_PC * 32) / 8, 256, 0, 0>>>(x, y, 0);
    kgather<<<(ROWS_PC * 32) / 8, 256, 0, g_cs.s1>>>(x, y, BPC);

    cudaEventRecord(g_cs.join, g_cs.s1);
    cudaStreamWaitEvent(0, g_cs.join, 0);
}

// round 11
// speedup vs baseline: 1.1743x; 1.0355x over previous
#include <cuda_runtime.h>
#include <cstdint>

#define B 16
#define I 256
#define T 8192
#define NSTEP 8189   // T-3 sampled steps
#define TOUT  8190   // T-2 output length

#define BPC 8                 // batches per chain (2 chains)
#define ROWS_PC (BPC * I)     // rows per chain = 2048

// Scratch (static __device__ arrays; no allocation anywhere)
__device__ unsigned char g_nsp[B * T];       // [b][t]: bits0-1 = normal, bit2 = special-1
__device__ unsigned char g_delta[B * T];     // [b][jo]: gather delta in {0,1,2}

// ---------------- Threefry-2x32 (JAX-exact) ----------------
__device__ __forceinline__ void tf2x32(uint32_t k1, uint32_t k2,
                                       uint32_t c0, uint32_t c1,
                                       uint32_t& o0, uint32_t& o1) {
    uint32_t ks2 = k1 ^ k2 ^ 0x1BD11BDAu;
    uint32_t x0 = c0 + k1;
    uint32_t x1 = c1 + k2;
#define TFR(r) { x0 += x1; x1 = __funnelshift_l(x1, x1, (r)); x1 ^= x0; }
    TFR(13) TFR(15) TFR(26) TFR(6)
    x0 += k2;  x1 += ks2 + 1u;
    TFR(17) TFR(29) TFR(16) TFR(24)
    x0 += ks2; x1 += k1 + 2u;
    TFR(13) TFR(15) TFR(26) TFR(6)
    x0 += k1;  x1 += k2 + 3u;
    TFR(17) TFR(29) TFR(16) TFR(24)
    x0 += k2;  x1 += ks2 + 4u;
    TFR(13) TFR(15) TFR(26) TFR(6)
    x0 += ks2; x1 += k1 + 5u;
#undef TFR
    o0 = x0; o1 = x1;
}

// gumbel from 32 random bits, replicating jax._src.random._uniform + gumbel
__device__ __forceinline__ float gumbel_bits(uint32_t bits) {
    const float TINY = 1.17549435e-38f;   // finfo(float32).tiny
    float f = __uint_as_float((bits >> 9) | 0x3F800000u) - 1.0f;  // [0,1)
    float u = fmaxf(TINY, f + TINY);
    return -logf(-logf(u));
}

// ---------------- Kernel 1: draws for one chain (8 batches) ----------------
// 768 threads = 32 t x 8 b x 3 k. One draw threefry+gumbel per thread;
// per-step keys deduped via smem; k==0 threads combine the three gumbels.
__global__ __launch_bounds__(768) void kgen(const int* __restrict__ seedp, int b0) {
    __shared__ uint2 skey[32];
    __shared__ float sg[3 * 256];

    int tid = threadIdx.x;
    int k   = tid >> 8;                 // 0..2
    int idx = tid & 255;                // (bb, tt)
    int tt  = idx & 31;
    int bb  = idx >> 5;                 // 0..7
    int b   = b0 + bb;
    int t   = blockIdx.x * 32 + tt;

    uint32_t seed_lo = (uint32_t)(*seedp);  // threefry_seed: k1 = seed>>32 = 0

    if (tid < 32) {
        uint32_t kx, ky;
        tf2x32(0u, seed_lo, 0u, (uint32_t)(blockIdx.x * 32 + tid), kx, ky);
        skey[tid] = make_uint2(kx, ky);
    }
    __syncthreads();

    uint2 key = skey[tt];
    uint32_t o0, o1;
    tf2x32(key.x, key.y, 0u, (uint32_t)(b * 3 + k), o0, o1);
    sg[k * 256 + idx] = gumbel_bits(o0 ^ o1);
    __syncthreads();

    if (k == 0 && t < NSTEP) {
        float g0 = sg[idx];
        float g1 = sg[256 + idx];
        float g2 = sg[512 + idx];

        const double pd = 0.1, sd = 1.0 - 2.0 * 0.1;
        float lp  = logf(0.1f);
        float ls  = logf(0.8f);
        float l1s = logf((float)(sd / (pd + sd)));  // special row k=1
        float l2s = logf((float)(pd / (pd + sd)));  // special row k=2  (k=0 -inf)

        // normal row argmax (first max wins)
        float v0 = g0 + lp, v1 = g1 + ls, v2 = g2 + lp;
        int n = 0; float best = v0;
        if (v1 > best) { best = v1; n = 1; }
        if (v2 > best) { n = 2; }

        // special row argmax over {1,2}
        int sp = (g2 + l2s > g1 + l1s) ? 2 : 1;

        g_nsp[b * T + t] = (unsigned char)(n | ((sp - 1) << 2));
    }
}

// ---------------- Class-domain FSM machinery ----------------
// State v = 3*p2+p1 in [0,9); class(v): v==5 -> 3, else v%3.
// classLUT packed 2b: v=0..8 -> 0,1,2,0,1,3,0,1,2  = 0x24D24.
// Key identity: v % 3 == min(class(v), 2)  -> choices recoverable from class.
// A map = 4 bytes, byte c = class reached starting from class c (values 0..3).

// compose: apply p then c. result byte i = c[p[i]]. PRMT-based.
__device__ __forceinline__ uint32_t compose(uint32_t p, uint32_t c) {
    uint32_t u   = (p | (p >> 4)) & 0x00FF00FFu;   // byte0=p0|p1<<4, byte2=p2|p3<<4
    uint32_t sel = u | (u >> 8);                   // nibbles [p0,p1,p2,p3]
    return __byte_perm(c, 0u, sel);
}

// single-step class map from an nsp byte.
// classes (0,1,2,3) step to classes (n, n+(n==2), n, sp).
__device__ __forceinline__ uint32_t stepmap(uint32_t byt) {
    uint32_t n   = byt & 3u;
    uint32_t is2 = (n == 2u) ? 1u : 0u;
    uint32_t sp  = 1u + ((byt >> 2) & 1u);
    return n * 0x00010101u + (is2 << 8) + (sp << 24);
}

// ---------------- Kernel 2: class-domain parallel FSM scan, 1 block/batch --
// 1024 threads x 8 steps. Chunk build + warp scan + block scan over 4-byte
// class maps; emit packs 8 delta bytes per thread into ONE aligned STG.64
// (byte0 = previous step's choice = min(entry_class,2); for j==0 the init
// state 4 has class 1 -> byte0 = 1 = the fixed dp[0]).
__global__ __launch_bounds__(1024) void kscan(int b0) {
    int b = b0 + blockIdx.x;
    int j = threadIdx.x;               // 0..1023, chunk of 8 steps
    int lane = j & 31, warp = j >> 5;  // 32 warps
    __shared__ uint32_t wtot[32];
    __shared__ uint32_t incl_s[1024];

    // g_nsp row tail bytes (t >= NSTEP) are never written -> always 0 ->
    // deterministic garbage that only lands in unused g_delta[8190..8191].
    uint2 wv = __ldg(reinterpret_cast<const uint2*>(g_nsp + b * T + j * 8));
    uint32_t w[2] = {wv.x, wv.y};

    // chunk map: 8 steps, no validity guards needed (see above)
    uint32_t incl = stepmap(w[0] & 0xFFu);
#pragma unroll
    for (int s = 1; s < 8; s++)
        incl = compose(incl, stepmap((w[s >> 2] >> ((s & 3) * 8)) & 0xFFu));

    // warp-level inclusive scan of composition
#pragma unroll
    for (int off = 1; off < 32; off <<= 1) {
        uint32_t p = __shfl_up_sync(0xFFFFFFFFu, incl, off);
        if (lane >= off) incl = compose(p, incl);
    }
    if (lane == 31) wtot[warp] = incl;
    __syncthreads();

    // warp 0 scans the 32 warp totals
    if (warp == 0) {
        uint32_t v = wtot[lane];
#pragma unroll
        for (int off = 1; off < 32; off <<= 1) {
            uint32_t p = __shfl_up_sync(0xFFFFFFFFu, v, off);
            if (lane >= off) v = compose(p, v);
        }
        wtot[lane] = v;
    }
    __syncthreads();

    if (warp > 0) incl = compose(wtot[warp - 1], incl);
    incl_s[j] = incl;
    __syncthreads();

    // entry class: init state 4 = class 1 -> byte1 of prefix map
    uint32_t cl = (j == 0) ? 1u : ((incl_s[j - 1] >> 8) & 3u);

    // emit 8 delta bytes: byte0 = min(cl,2) (prev step's choice / fixed 1),
    // bytes 1..7 = choices of this chunk's first 7 steps.
    uint32_t m = (cl == 3u) ? 2u : cl;
    uint32_t lo = m, hi = 0;
#pragma unroll
    for (int s = 0; s < 7; s++) {
        uint32_t byt = (w[s >> 2] >> ((s & 3) * 8)) & 0xFFu;
        uint32_t n = byt & 3u, sp = 1u + ((byt >> 2) & 1u);
        uint32_t ch = (cl == 3u) ? sp : n;
        if (s < 3) lo |= ch << (8 * (s + 1));
        else       hi |= ch << (8 * (s - 3));
        uint32_t st = m * 3u + ch;
        cl = (0x24D24u >> (2u * st)) & 3u;
        m  = (cl == 3u) ? 2u : cl;
    }
    *reinterpret_cast<uint2*>(g_delta + b * T + j * 8) = make_uint2(lo, hi);
}

// ---------------- Kernel 3: barrier-free warp gather, 8 outputs/thread ----
__global__ __launch_bounds__(256) void kgather(const float* __restrict__ x,
                                               float* __restrict__ y, int b0) {
    int gw   = blockIdx.x * 8 + (threadIdx.x >> 5);  // warp id within chain
    int lane = threadIdx.x & 31;
    int row  = b0 * I + (gw >> 5);                   // b*I + i (32 warps/row)
    int wseg = gw & 31;
    int wb   = wseg << 8;                            // warp base within row
    int b    = row >> 8;
    bool last = (wseg == 31);                        // row tail warp

    const float* xr = x + (size_t)row * T + wb;
    float4 a = __ldcs(reinterpret_cast<const float4*>(xr) + lane * 2);
    float4 c = __ldcs(reinterpret_cast<const float4*>(xr) + lane * 2 + 1);
    uint2 dd = *reinterpret_cast<const uint2*>(g_delta + (size_t)b * T + wb + lane * 8);

    float ex0 = 0.f, ex1 = 0.f;
    if (!last && lane == 0) {
        float2 e = __ldg(reinterpret_cast<const float2*>(xr + 256));
        ex0 = e.x; ex1 = e.y;
    }
    ex0 = __shfl_sync(0xFFFFFFFFu, ex0, 0);
    ex1 = __shfl_sync(0xFFFFFFFFu, ex1, 0);

    float nx = __shfl_down_sync(0xFFFFFFFFu, a.x, 1);
    float ny = __shfl_down_sync(0xFFFFFFFFu, a.y, 1);
    if (lane == 31) { nx = ex0; ny = ex1; }

    float rr[10] = {a.x, a.y, a.z, a.w, c.x, c.y, c.z, c.w, nx, ny};
    float o[8];
#pragma unroll
    for (int q = 0; q < 8; q++) {
        uint32_t d = ((q < 4 ? dd.x >> (8 * q) : dd.y >> (8 * (q - 4))) & 3u);
        o[q] = (d == 0) ? rr[q] : ((d == 1) ? rr[q + 1] : rr[q + 2]);
    }

    float* yr = y + (size_t)row * TOUT + wb + lane * 8;
    bool tail = last && (lane == 31);
    if (!tail) {
        if ((row & 1) == 0) {
            __stcs(reinterpret_cast<float4*>(yr),     make_float4(o[0], o[1], o[2], o[3]));
            __stcs(reinterpret_cast<float4*>(yr) + 1, make_float4(o[4], o[5], o[6], o[7]));
        } else {
            __stcs(reinterpret_cast<float2*>(yr),     make_float2(o[0], o[1]));
            __stcs(reinterpret_cast<float2*>(yr) + 1, make_float2(o[2], o[3]));
            __stcs(reinterpret_cast<float2*>(yr) + 2, make_float2(o[4], o[5]));
            __stcs(reinterpret_cast<float2*>(yr) + 3, make_float2(o[6], o[7]));
        }
    } else {
        __stcs(reinterpret_cast<float2*>(yr),     make_float2(o[0], o[1]));
        __stcs(reinterpret_cast<float2*>(yr) + 1, make_float2(o[2], o[3]));
        __stcs(reinterpret_cast<float2*>(yr) + 2, make_float2(o[4], o[5]));
    }
}

// ---------------- One extra stream + 2 events (handles only, no dev mem) ---
struct ChainStreams {
    cudaStream_t s1;
    cudaEvent_t  fork, join;
    ChainStreams() {
        cudaStreamCreateWithFlags(&s1, cudaStreamNonBlocking);
        cudaEventCreateWithFlags(&fork, cudaEventDisableTiming);
        cudaEventCreateWithFlags(&join, cudaEventDisableTiming);
    }
};
static ChainStreams g_cs;

extern "C" void kernel_launch(void* const* d_in, const int* in_sizes, int n_in,
                              void* d_out, int out_size) {
    const float* x   = (const float*)d_in[0];
    const int* seedp = (const int*)d_in[1];
    float* y = (float*)d_out;

    cudaEventRecord(g_cs.fork, 0);
    cudaStreamWaitEvent(g_cs.s1, g_cs.fork, 0);

    // prologues first (adjacent in submission order), then gathers
    kgen<<<(NSTEP + 31) / 32, 768, 0, 0>>>(seedp, 0);
    kgen<<<(NSTEP + 31) / 32, 768, 0, g_cs.s1>>>(seedp, BPC);
    kscan<<<BPC, 1024, 0, 0>>>(0);
    kscan<<<BPC, 1024, 0, g_cs.s1>>>(BPC);
    kgather<<<(ROWS_PC * 32) / 8, 256, 0, 0>>>(x, y, 0);
    kgather<<<(ROWS_PC * 32) / 8, 256, 0, g_cs.s1>>>(x, y, BPC);

    cudaEventRecord(g_cs.join, g_cs.s1);
    cudaStreamWaitEvent(0, g_cs.join, 0);
}

// round 12
// speedup vs baseline: 1.1812x; 1.0058x over previous
#include <cuda_runtime.h>
#include <cstdint>

#define B 16
#define I 256
#define T 8192
#define NSTEP 8189   // T-3 sampled steps
#define TOUT  8190   // T-2 output length

#define BPC 8                 // batches per chain (2 chains)
#define ROWS_PC (BPC * I)     // rows per chain = 2048

// Scratch (static __device__ arrays; no allocation anywhere)
__device__ unsigned char g_nsp[B * T];       // [b][t]: bits0-1 = normal, bit2 = special-1
__device__ unsigned char g_delta[B * T];     // [b][jo]: gather delta in {0,1,2}

// ---------------- Threefry-2x32 (JAX-exact) ----------------
__device__ __forceinline__ void tf2x32(uint32_t k1, uint32_t k2,
                                       uint32_t c0, uint32_t c1,
                                       uint32_t& o0, uint32_t& o1) {
    uint32_t ks2 = k1 ^ k2 ^ 0x1BD11BDAu;
    uint32_t x0 = c0 + k1;
    uint32_t x1 = c1 + k2;
#define TFR(r) { x0 += x1; x1 = __funnelshift_l(x1, x1, (r)); x1 ^= x0; }
    TFR(13) TFR(15) TFR(26) TFR(6)
    x0 += k2;  x1 += ks2 + 1u;
    TFR(17) TFR(29) TFR(16) TFR(24)
    x0 += ks2; x1 += k1 + 2u;
    TFR(13) TFR(15) TFR(26) TFR(6)
    x0 += k1;  x1 += k2 + 3u;
    TFR(17) TFR(29) TFR(16) TFR(24)
    x0 += k2;  x1 += ks2 + 4u;
    TFR(13) TFR(15) TFR(26) TFR(6)
    x0 += ks2; x1 += k1 + 5u;
#undef TFR
    o0 = x0; o1 = x1;
}

// gumbel from 32 random bits, replicating jax._src.random._uniform + gumbel
__device__ __forceinline__ float gumbel_bits(uint32_t bits) {
    const float TINY = 1.17549435e-38f;   // finfo(float32).tiny
    float f = __uint_as_float((bits >> 9) | 0x3F800000u) - 1.0f;  // [0,1)
    float u = fmaxf(TINY, f + TINY);
    return -logf(-logf(u));
}

// ---------------- Kernel 1: draws for one chain (8 batches) ----------------
// 256 threads = 32 t x 8 b. Each thread does ALL 3 draws for its (t,b):
// three independent threefry chains interleave for ILP; argmax in registers
// (no gumbel exchange, single barrier). Keys deduped via smem.
__global__ __launch_bounds__(256) void kgen(const int* __restrict__ seedp, int b0) {
    __shared__ uint2 skey[32];

    int tid = threadIdx.x;
    int tt  = tid & 31;
    int b   = b0 + (tid >> 5);          // 8 batches per chain
    int t   = blockIdx.x * 32 + tt;

    uint32_t seed_lo = (uint32_t)(*seedp);  // threefry_seed: k1 = seed>>32 = 0

    if (tid < 32) {
        uint32_t kx, ky;
        tf2x32(0u, seed_lo, 0u, (uint32_t)(blockIdx.x * 32 + tid), kx, ky);
        skey[tid] = make_uint2(kx, ky);
    }
    __syncthreads();

    if (t >= NSTEP) return;
    uint2 key = skey[tt];

    // three independent threefries (compiler interleaves -> 3-way ILP)
    uint32_t a0, a1, b0_, b1_, c0_, c1_;
    tf2x32(key.x, key.y, 0u, (uint32_t)(b * 3 + 0), a0, a1);
    tf2x32(key.x, key.y, 0u, (uint32_t)(b * 3 + 1), b0_, b1_);
    tf2x32(key.x, key.y, 0u, (uint32_t)(b * 3 + 2), c0_, c1_);
    float g0 = gumbel_bits(a0 ^ a1);
    float g1 = gumbel_bits(b0_ ^ b1_);
    float g2 = gumbel_bits(c0_ ^ c1_);

    const double pd = 0.1, sd = 1.0 - 2.0 * 0.1;
    float lp  = logf(0.1f);
    float ls  = logf(0.8f);
    float l1s = logf((float)(sd / (pd + sd)));  // special row k=1
    float l2s = logf((float)(pd / (pd + sd)));  // special row k=2  (k=0 -inf)

    // normal row argmax (first max wins)
    float v0 = g0 + lp, v1 = g1 + ls, v2 = g2 + lp;
    int n = 0; float best = v0;
    if (v1 > best) { best = v1; n = 1; }
    if (v2 > best) { n = 2; }

    // special row argmax over {1,2}
    int sp = (g2 + l2s > g1 + l1s) ? 2 : 1;

    g_nsp[b * T + t] = (unsigned char)(n | ((sp - 1) << 2));
}

// ---------------- Class-domain FSM machinery ----------------
// State v = 3*p2+p1 in [0,9); class(v): v==5 -> 3, else v%3.
// Key identity: v % 3 == min(class(v), 2)  -> choices recoverable from class.
// A map = 4 bytes, byte c = class reached starting from class c (values 0..3).

// compose: apply p then c. result byte i = c[p[i]]. PRMT-based.
__device__ __forceinline__ uint32_t compose(uint32_t p, uint32_t c) {
    uint32_t u   = (p | (p >> 4)) & 0x00FF00FFu;   // byte0=p0|p1<<4, byte2=p2|p3<<4
    uint32_t sel = u | (u >> 8);                   // nibbles [p0,p1,p2,p3]
    return __byte_perm(c, 0u, sel);
}

// single-step class map from an nsp byte.
// classes (0,1,2,3) step to classes (n, n+(n==2), n, sp).
__device__ __forceinline__ uint32_t stepmap(uint32_t byt) {
    uint32_t n   = byt & 3u;
    uint32_t is2 = (n == 2u) ? 1u : 0u;
    uint32_t sp  = 1u + ((byt >> 2) & 1u);
    return n * 0x00010101u + (is2 << 8) + (sp << 24);
}

// ---------------- Kernel 2: class-domain parallel FSM scan, 1 block/batch --
// 1024 threads x 8 steps. ONE barrier: warp scan -> wtot smem -> every warp
// redundantly scans the 32 warp totals (no warp-0 serialization), exclusive
// maps via shfl_up (no smem round-trip). Emit is ILP: classes extracted from
// register-held chunk partial maps; one aligned 8-byte store.
__global__ __launch_bounds__(1024) void kscan(int b0) {
    int b = b0 + blockIdx.x;
    int j = threadIdx.x;               // 0..1023, chunk of 8 steps
    int lane = j & 31, warp = j >> 5;  // 32 warps
    __shared__ uint32_t wtot[32];

    // g_nsp tail bytes (t >= NSTEP) are never written -> 0 -> deterministic
    // garbage only lands in unused g_delta[8190..8191].
    uint2 wv = __ldg(reinterpret_cast<const uint2*>(g_nsp + b * T + j * 8));
    uint32_t w[2] = {wv.x, wv.y};

    // chunk partial maps cm[s] = steps 0..s (kept for ILP emit)
    uint32_t cm[7];
    cm[0] = stepmap(w[0] & 0xFFu);
#pragma unroll
    for (int s = 1; s < 7; s++)
        cm[s] = compose(cm[s - 1], stepmap((w[s >> 2] >> ((s & 3) * 8)) & 0xFFu));
    uint32_t incl = compose(cm[6], stepmap(w[1] >> 24));

    // warp-level inclusive scan of composition
#pragma unroll
    for (int off = 1; off < 32; off <<= 1) {
        uint32_t p = __shfl_up_sync(0xFFFFFFFFu, incl, off);
        if (lane >= off) incl = compose(p, incl);
    }
    if (lane == 31) wtot[warp] = incl;
    __syncthreads();

    // every warp redundantly scans the 32 warp totals; takes its own prefix
    uint32_t v = wtot[lane];
#pragma unroll
    for (int off = 1; off < 32; off <<= 1) {
        uint32_t p = __shfl_up_sync(0xFFFFFFFFu, v, off);
        if (lane >= off) v = compose(p, v);
    }
    uint32_t pw = __shfl_sync(0xFFFFFFFFu, v, (warp > 0) ? (warp - 1) : 0);
    if (warp > 0) incl = compose(pw, incl);

    // exclusive map -> entry class (init state 4 = class 1 -> byte1)
    uint32_t e = __shfl_up_sync(0xFFFFFFFFu, incl, 1);
    if (lane == 0) e = pw;             // warp>0 lane0; warp0 lane0 unused
    uint32_t cl0 = (j == 0) ? 1u : ((e >> 8) & 3u);

    // ILP emit: byte0 = min(cl0,2); class before step s from cm[s-1].
    uint32_t m0 = (cl0 == 3u) ? 2u : cl0;
    uint32_t lo = m0, hi = 0;
#pragma unroll
    for (int s = 0; s < 7; s++) {
        uint32_t cls = (s == 0) ? cl0 : ((cm[s - 1] >> (8u * cl0)) & 3u);
        uint32_t byt = (w[s >> 2] >> ((s & 3) * 8)) & 0xFFu;
        uint32_t n = byt & 3u, sp = 1u + ((byt >> 2) & 1u);
        uint32_t ch = (cls == 3u) ? sp : n;
        if (s < 3) lo |= ch << (8 * (s + 1));
        else       hi |= ch << (8 * (s - 3));
    }
    *reinterpret_cast<uint2*>(g_delta + b * T + j * 8) = make_uint2(lo, hi);
}

// ---------------- Kernel 3: barrier-free warp gather, 8 outputs/thread ----
__global__ __launch_bounds__(256) void kgather(const float* __restrict__ x,
                                               float* __restrict__ y, int b0) {
    int gw   = blockIdx.x * 8 + (threadIdx.x >> 5);  // warp id within chain
    int lane = threadIdx.x & 31;
    int row  = b0 * I + (gw >> 5);                   // b*I + i (32 warps/row)
    int wseg = gw & 31;
    int wb   = wseg << 8;                            // warp base within row
    int b    = row >> 8;
    bool last = (wseg == 31);                        // row tail warp

    const float* xr = x + (size_t)row * T + wb;
    float4 a = __ldcs(reinterpret_cast<const float4*>(xr) + lane * 2);
    float4 c = __ldcs(reinterpret_cast<const float4*>(xr) + lane * 2 + 1);
    uint2 dd = *reinterpret_cast<const uint2*>(g_delta + (size_t)b * T + wb + lane * 8);

    float ex0 = 0.f, ex1 = 0.f;
    if (!last && lane == 0) {
        float2 e = __ldg(reinterpret_cast<const float2*>(xr + 256));
        ex0 = e.x; ex1 = e.y;
    }
    ex0 = __shfl_sync(0xFFFFFFFFu, ex0, 0);
    ex1 = __shfl_sync(0xFFFFFFFFu, ex1, 0);

    float nx = __shfl_down_sync(0xFFFFFFFFu, a.x, 1);
    float ny = __shfl_down_sync(0xFFFFFFFFu, a.y, 1);
    if (lane == 31) { nx = ex0; ny = ex1; }

    float rr[10] = {a.x, a.y, a.z, a.w, c.x, c.y, c.z, c.w, nx, ny};
    float o[8];
#pragma unroll
    for (int q = 0; q < 8; q++) {
        uint32_t d = ((q < 4 ? dd.x >> (8 * q) : dd.y >> (8 * (q - 4))) & 3u);
        o[q] = (d == 0) ? rr[q] : ((d == 1) ? rr[q + 1] : rr[q + 2]);
    }

    float* yr = y + (size_t)row * TOUT + wb + lane * 8;
    bool tail = last && (lane == 31);
    if (!tail) {
        if ((row & 1) == 0) {
            __stcs(reinterpret_cast<float4*>(yr),     make_float4(o[0], o[1], o[2], o[3]));
            __stcs(reinterpret_cast<float4*>(yr) + 1, make_float4(o[4], o[5], o[6], o[7]));
        } else {
            __stcs(reinterpret_cast<float2*>(yr),     make_float2(o[0], o[1]));
            __stcs(reinterpret_cast<float2*>(yr) + 1, make_float2(o[2], o[3]));
            __stcs(reinterpret_cast<float2*>(yr) + 2, make_float2(o[4], o[5]));
            __stcs(reinterpret_cast<float2*>(yr) + 3, make_float2(o[6], o[7]));
        }
    } else {
        __stcs(reinterpret_cast<float2*>(yr),     make_float2(o[0], o[1]));
        __stcs(reinterpret_cast<float2*>(yr) + 1, make_float2(o[2], o[3]));
        __stcs(reinterpret_cast<float2*>(yr) + 2, make_float2(o[4], o[5]));
    }
}

// ---------------- One extra stream + 2 events (handles only, no dev mem) ---
struct ChainStreams {
    cudaStream_t s1;
    cudaEvent_t  fork, join;
    ChainStreams() {
        cudaStreamCreateWithFlags(&s1, cudaStreamNonBlocking);
        cudaEventCreateWithFlags(&fork, cudaEventDisableTiming);
        cudaEventCreateWithFlags(&join, cudaEventDisableTiming);
    }
};
static ChainStreams g_cs;

extern "C" void kernel_launch(void* const* d_in, const int* in_sizes, int n_in,
                              void* d_out, int out_size) {
    const float* x   = (const float*)d_in[0];
    const int* seedp = (const int*)d_in[1];
    float* y = (float*)d_out;

    cudaEventRecord(g_cs.fork, 0);
    cudaStreamWaitEvent(g_cs.s1, g_cs.fork, 0);

    // prologues first (adjacent in submission order), then gathers
    kgen<<<(NSTEP + 31) / 32, 256, 0, 0>>>(seedp, 0);
    kgen<<<(NSTEP + 31) / 32, 256, 0, g_cs.s1>>>(seedp, BPC);
    kscan<<<BPC, 1024, 0, 0>>>(0);
    kscan<<<BPC, 1024, 0, g_cs.s1>>>(BPC);
    kgather<<<(ROWS_PC * 32) / 8, 256, 0, 0>>>(x, y, 0);
    kgather<<<(ROWS_PC * 32) / 8, 256, 0, g_cs.s1>>>(x, y, BPC);

    cudaEventRecord(g_cs.join, g_cs.s1);
    cudaStreamWaitEvent(0, g_cs.join, 0);
}